// round 3
// baseline (speedup 1.0000x reference)
#include <cuda_runtime.h>
#include <stdint.h>

// VDEmbedding: out[b,s,:] = (x[b,s]==0 ? 0 : mask[x[b,s]]) * weight[x[b,s], :]
// x: int32 [65536], weight: f32 [128000,128], mask: f32 [128000] -> out: f32 [65536,128]
//
// R2: 4 tokens per warp, loads front-batched for MLP=4 per thread; streaming
// stores (__stcs) to keep the weight table resident in L2 across replays.

static constexpr int EMBED_DIM = 128;
static constexpr int PAD_IDX = 0;
static constexpr int TOK_PER_WARP = 4;

__global__ __launch_bounds__(256)
void vdemb_kernel(const int* __restrict__ x,
                  const float* __restrict__ weight,
                  const float* __restrict__ mask,
                  float* __restrict__ out,
                  int n_tokens)
{
    int warp_in_block = threadIdx.x >> 5;
    int lane = threadIdx.x & 31;
    int warp_global = blockIdx.x * (blockDim.x >> 5) + warp_in_block;
    int base_token = warp_global * TOK_PER_WARP;
    if (base_token >= n_tokens) return;  // grid sized exactly; tail never hit for 64Ki

    // 1) batch the index loads (broadcast within warp, 4 independent)
    int idx[TOK_PER_WARP];
#pragma unroll
    for (int i = 0; i < TOK_PER_WARP; i++)
        idx[i] = __ldg(&x[base_token + i]);

    // 2) batch the mask loads (4 independent)
    float s[TOK_PER_WARP];
#pragma unroll
    for (int i = 0; i < TOK_PER_WARP; i++)
        s[i] = (idx[i] == PAD_IDX) ? 0.0f : __ldg(&mask[idx[i]]);

    // 3) batch the row gathers: 4 independent LDG.E.128 in flight per thread
    float4 w[TOK_PER_WARP];
#pragma unroll
    for (int i = 0; i < TOK_PER_WARP; i++) {
        const float4* wrow =
            reinterpret_cast<const float4*>(weight + (size_t)idx[i] * EMBED_DIM);
        w[i] = __ldg(&wrow[lane]);
    }

    // 4) scale + streaming stores (evict-first: don't pollute L2 with output)
#pragma unroll
    for (int i = 0; i < TOK_PER_WARP; i++) {
        float4 o;
        o.x = s[i] * w[i].x;
        o.y = s[i] * w[i].y;
        o.z = s[i] * w[i].z;
        o.w = s[i] * w[i].w;
        float4* orow =
            reinterpret_cast<float4*>(out + (size_t)(base_token + i) * EMBED_DIM);
        __stcs(&orow[lane], o);
    }
}

extern "C" void kernel_launch(void* const* d_in, const int* in_sizes, int n_in,
                              void* d_out, int out_size)
{
    const int*   x      = (const int*)d_in[0];
    const float* weight = (const float*)d_in[1];
    const float* mask   = (const float*)d_in[2];
    float*       out    = (float*)d_out;

    int n_tokens = in_sizes[0];                      // 65536
    int tokens_per_block = (256 / 32) * TOK_PER_WARP; // 32
    int blocks = (n_tokens + tokens_per_block - 1) / tokens_per_block; // 2048

    vdemb_kernel<<<blocks, 256>>>(x, weight, mask, out, n_tokens);
}

// round 4
// speedup vs baseline: 1.0239x; 1.0239x over previous
#include <cuda_runtime.h>
#include <stdint.h>

// VDEmbedding: out[t,:] = (x[t]==0 ? 0 : mask[x[t]]) * weight[x[t], :]
// x: int32 [65536], weight: f32 [128000,128], mask: f32 [128000] -> out: f32 [65536,128]
//
// R3: cp.async deep-pipelined gather (8 tokens x 512B per warp in flight, zero
// register cost), single fully-resident wave (1024 blocks, 7 blocks/SM via 32KB smem).

static constexpr int EMBED_DIM = 128;
static constexpr int PAD_IDX   = 0;
static constexpr int TOK       = 8;    // tokens per warp
static constexpr int WARPS     = 8;    // warps per block
static constexpr int ROW_BYTES = EMBED_DIM * 4;  // 512

__global__ __launch_bounds__(256, 7)
void vdemb_kernel(const int* __restrict__ x,
                  const float* __restrict__ weight,
                  const float* __restrict__ mask,
                  float* __restrict__ out,
                  int n_tokens)
{
    __shared__ __align__(16) float smem[WARPS * TOK * EMBED_DIM];  // 32 KB

    int warp = threadIdx.x >> 5;
    int lane = threadIdx.x & 31;
    int base = (blockIdx.x * WARPS + warp) * TOK;

    // u32 shared address of this warp's staging area
    uint32_t s_base;
    {
        const void* p = &smem[warp * TOK * EMBED_DIM];
        asm("{ .reg .u64 t; cvta.to.shared.u64 t, %1; cvt.u32.u64 %0, t; }"
            : "=r"(s_base) : "l"(p));
    }

    // 1) index loads (broadcast, 1 line)
    int idx[TOK];
#pragma unroll
    for (int i = 0; i < TOK; i++) {
        int t = base + i;
        idx[i] = (t < n_tokens) ? __ldg(&x[t]) : PAD_IDX;
    }

    // 2) fire-and-forget async gather: 8 rows x 512B per warp in flight
#pragma unroll
    for (int i = 0; i < TOK; i++) {
        const float* src = weight + (size_t)idx[i] * EMBED_DIM + lane * 4;
        uint32_t dst = s_base + (uint32_t)(i * ROW_BYTES + lane * 16);
        asm volatile("cp.async.cg.shared.global [%0], [%1], 16;"
                     :: "r"(dst), "l"(src));
    }
    asm volatile("cp.async.commit_group;");

    // 3) mask gathers overlap with the async copies
    float s[TOK];
#pragma unroll
    for (int i = 0; i < TOK; i++)
        s[i] = (idx[i] == PAD_IDX) ? 0.0f : __ldg(&mask[idx[i]]);

    asm volatile("cp.async.wait_group 0;" ::: "memory");
    // each lane reads exactly the bytes it copied -> no cross-lane hazard, no barrier

    // 4) scale + streaming store
#pragma unroll
    for (int i = 0; i < TOK; i++) {
        int t = base + i;
        if (t < n_tokens) {
            const float4* sp =
                reinterpret_cast<const float4*>(&smem[(warp * TOK + i) * EMBED_DIM]);
            float4 w = sp[lane];
            float4 o;
            o.x = s[i] * w.x;
            o.y = s[i] * w.y;
            o.z = s[i] * w.z;
            o.w = s[i] * w.w;
            float4* orow = reinterpret_cast<float4*>(out + (size_t)t * EMBED_DIM);
            __stcs(&orow[lane], o);
        }
    }
}

extern "C" void kernel_launch(void* const* d_in, const int* in_sizes, int n_in,
                              void* d_out, int out_size)
{
    const int*   x      = (const int*)d_in[0];
    const float* weight = (const float*)d_in[1];
    const float* mask   = (const float*)d_in[2];
    float*       out    = (float*)d_out;

    int n_tokens = in_sizes[0];                    // 65536
    int tokens_per_block = WARPS * TOK;            // 64
    int blocks = (n_tokens + tokens_per_block - 1) / tokens_per_block;  // 1024

    vdemb_kernel<<<blocks, 256>>>(x, weight, mask, out, n_tokens);
}